// round 1
// baseline (speedup 1.0000x reference)
#include <cuda_runtime.h>

#define MDIM 1024
#define RANK 128
#define NBATCH 8
#define SEQ 512

// Scratch for the projected activations T = batch @ proj : [8*512, 128] fp32 = 2 MB.
// Static __device__ array (no allocations allowed in kernel_launch).
__device__ float g_T[NBATCH * SEQ * RANK];

// ---------------------------------------------------------------------------
// Kernel 1: T[4096,128] = A[4096,1024] @ B[1024,128]
// Tiled fp32 GEMM: BM=64, BN=64, BK=16, 256 threads, 4x4 register tile/thread.
// Grid: (128/64=2, 4096/64=64) = 128 blocks.
// ---------------------------------------------------------------------------
__global__ void __launch_bounds__(256) proj_gemm_kernel(
    const float* __restrict__ A, const float* __restrict__ B)
{
    const int BM = 64, BN = 64, BK = 16;
    __shared__ float As[BM][BK + 1];   // +1 pad
    __shared__ float Bs[BK][BN + 1];   // +1 pad

    const int tid = threadIdx.x;
    const int tx = tid & 15;          // 0..15 -> N direction
    const int ty = tid >> 4;          // 0..15 -> M direction
    const int rb = blockIdx.y * BM;
    const int cb = blockIdx.x * BN;

    float acc[4][4] = {};

    for (int kt = 0; kt < MDIM; kt += BK) {
        // Load A tile: 64x16 floats = 256 float4 (1 per thread)
        {
            int r  = tid >> 2;        // row 0..63 (4 float4 per row)
            int k4 = tid & 3;         // which float4 in the row
            float4 v = *(const float4*)&A[(size_t)(rb + r) * MDIM + kt + k4 * 4];
            As[r][k4 * 4 + 0] = v.x;
            As[r][k4 * 4 + 1] = v.y;
            As[r][k4 * 4 + 2] = v.z;
            As[r][k4 * 4 + 3] = v.w;
        }
        // Load B tile: 16x64 floats = 256 float4 (1 per thread)
        {
            int k  = tid >> 4;        // row 0..15 (16 float4 per row)
            int c4 = tid & 15;
            float4 v = *(const float4*)&B[(size_t)(kt + k) * RANK + cb + c4 * 4];
            Bs[k][c4 * 4 + 0] = v.x;
            Bs[k][c4 * 4 + 1] = v.y;
            Bs[k][c4 * 4 + 2] = v.z;
            Bs[k][c4 * 4 + 3] = v.w;
        }
        __syncthreads();

        #pragma unroll
        for (int k = 0; k < BK; k++) {
            float a[4], b[4];
            #pragma unroll
            for (int r = 0; r < 4; r++) a[r] = As[ty * 4 + r][k];
            #pragma unroll
            for (int c = 0; c < 4; c++) b[c] = Bs[k][tx + 16 * c];
            #pragma unroll
            for (int r = 0; r < 4; r++)
                #pragma unroll
                for (int c = 0; c < 4; c++)
                    acc[r][c] = fmaf(a[r], b[c], acc[r][c]);
        }
        __syncthreads();
    }

    #pragma unroll
    for (int r = 0; r < 4; r++)
        #pragma unroll
        for (int c = 0; c < 4; c++)
            g_T[(size_t)(rb + ty * 4 + r) * RANK + cb + tx + 16 * c] = acc[r][c];
}

// ---------------------------------------------------------------------------
// Kernel 2: out[b,i,j] = sum_r (T[b,i,r] - T[b,j,r])^2
// 64x64 output tile per block, K processed in chunks of 32.
// Grid: (8 jtiles, 8 itiles, 8 batches), 256 threads, 4x4 per thread.
// j-columns strided by 16 per thread -> conflict-free Tj reads + coalesced-ish
// stores (16 consecutive floats per half-warp).
// ---------------------------------------------------------------------------
__global__ void __launch_bounds__(256) pdist_kernel(float* __restrict__ out)
{
    __shared__ float Ti[64][33];
    __shared__ float Tj[64][33];

    const int tid = threadIdx.x;
    const int tx = tid & 15;
    const int ty = tid >> 4;
    const int b  = blockIdx.z;
    const int i0 = blockIdx.y * 64;
    const int j0 = blockIdx.x * 64;

    const float* __restrict__ Tb = g_T + (size_t)b * SEQ * RANK;

    float acc[4][4] = {};

    #pragma unroll
    for (int kc = 0; kc < RANK; kc += 32) {
        // Load two 64x32 tiles = 512 float4 each; 256 threads -> 2 per thread
        #pragma unroll
        for (int t = 0; t < 2; t++) {
            int i  = tid + t * 256;
            int r  = i >> 3;          // 8 float4 per row
            int k4 = i & 7;
            float4 v = *(const float4*)&Tb[(size_t)(i0 + r) * RANK + kc + k4 * 4];
            Ti[r][k4 * 4 + 0] = v.x;
            Ti[r][k4 * 4 + 1] = v.y;
            Ti[r][k4 * 4 + 2] = v.z;
            Ti[r][k4 * 4 + 3] = v.w;
            float4 w = *(const float4*)&Tb[(size_t)(j0 + r) * RANK + kc + k4 * 4];
            Tj[r][k4 * 4 + 0] = w.x;
            Tj[r][k4 * 4 + 1] = w.y;
            Tj[r][k4 * 4 + 2] = w.z;
            Tj[r][k4 * 4 + 3] = w.w;
        }
        __syncthreads();

        #pragma unroll
        for (int kk = 0; kk < 32; kk++) {
            float a[4], bv[4];
            #pragma unroll
            for (int r = 0; r < 4; r++) a[r] = Ti[ty * 4 + r][kk];
            #pragma unroll
            for (int c = 0; c < 4; c++) bv[c] = Tj[tx + 16 * c][kk];
            #pragma unroll
            for (int r = 0; r < 4; r++)
                #pragma unroll
                for (int c = 0; c < 4; c++) {
                    float d = a[r] - bv[c];
                    acc[r][c] = fmaf(d, d, acc[r][c]);
                }
        }
        __syncthreads();
    }

    float* __restrict__ ob = out + (size_t)b * SEQ * SEQ;
    #pragma unroll
    for (int r = 0; r < 4; r++)
        #pragma unroll
        for (int c = 0; c < 4; c++)
            ob[(size_t)(i0 + ty * 4 + r) * SEQ + j0 + tx + 16 * c] = acc[r][c];
}

extern "C" void kernel_launch(void* const* d_in, const int* in_sizes, int n_in,
                              void* d_out, int out_size)
{
    const float* batch = (const float*)d_in[0];   // [8,512,1024]
    const float* proj  = (const float*)d_in[1];   // [1024,128]
    float* out = (float*)d_out;                   // [8,512,512]

    proj_gemm_kernel<<<dim3(2, 64), 256>>>(batch, proj);
    pdist_kernel<<<dim3(8, 8, 8), 256>>>(out);
}

// round 2
// speedup vs baseline: 1.3603x; 1.3603x over previous
#include <cuda_runtime.h>

#define MDIM 1024
#define RANK 128
#define NBATCH 8
#define SEQ 512
#define NROWS (NBATCH * SEQ)          // 4096
#define KSPLIT 4
#define KS (MDIM / KSPLIT)            // 256

// Scratch (static __device__ globals; no allocations allowed).
__device__ float g_Tp[KSPLIT][NROWS * RANK];   // K-split partials, 8 MB
__device__ float g_T[NROWS * RANK];            // combined T, 2 MB
__device__ float g_norm[NROWS];                // row squared norms

// Packed fp32x2 FMA (Blackwell FFMA2; only reachable via PTX).
__device__ __forceinline__ void ffma2(unsigned long long& d,
                                      unsigned long long a,
                                      unsigned long long b) {
    asm("fma.rn.f32x2 %0, %1, %2, %0;" : "+l"(d) : "l"(a), "l"(b));
}
__device__ __forceinline__ float f2lo(unsigned long long x) {
    return __uint_as_float((unsigned)(x & 0xffffffffu));
}
__device__ __forceinline__ float f2hi(unsigned long long x) {
    return __uint_as_float((unsigned)(x >> 32));
}

// ---------------------------------------------------------------------------
// Kernel 1: K-split GEMM  g_Tp[s] = A[:, s*256:(s+1)*256] @ B[s*256:...]
// BM=64, BN=128(full), BK=16, 256 threads, per-thread 4x8, FFMA2 k-paired.
// Grid: (KSPLIT=4, 64) = 256 blocks.
// ---------------------------------------------------------------------------
__global__ void __launch_bounds__(256) proj_gemm_kernel(
    const float* __restrict__ A, const float* __restrict__ B)
{
    __shared__ __align__(16) float As[64][20];    // row-major, stride 20 (16B-mult)
    __shared__ __align__(16) float Bst[128][18];  // transposed B tile [n][k]

    const int tid   = threadIdx.x;
    const int tx    = tid & 15;
    const int ty    = tid >> 4;
    const int split = blockIdx.x;
    const int rb    = blockIdx.y * 64;
    const int kbase = split * KS;

    unsigned long long acc[4][8];
    #pragma unroll
    for (int r = 0; r < 4; r++)
        #pragma unroll
        for (int c = 0; c < 8; c++) acc[r][c] = 0ull;

    for (int kk = 0; kk < KS; kk += 16) {
        const int kt = kbase + kk;
        // A tile 64x16: 256 float4, 1/thread, row-major into As
        {
            int r  = tid >> 2;
            int k4 = tid & 3;
            float4 v = *(const float4*)&A[(size_t)(rb + r) * MDIM + kt + k4 * 4];
            *(float4*)&As[r][k4 * 4] = v;
        }
        // B tile 16x128 -> transposed into Bst[n][k]: 512 float4, 2/thread
        #pragma unroll
        for (int t = 0; t < 2; t++) {
            int idx = tid + t * 256;
            int k   = idx >> 5;
            int n4  = idx & 31;
            float4 v = *(const float4*)&B[(size_t)(kt + k) * RANK + n4 * 4];
            Bst[n4 * 4 + 0][k] = v.x;
            Bst[n4 * 4 + 1][k] = v.y;
            Bst[n4 * 4 + 2][k] = v.z;
            Bst[n4 * 4 + 3][k] = v.w;
        }
        __syncthreads();

        #pragma unroll
        for (int k = 0; k < 16; k += 2) {
            unsigned long long a[4], b[8];
            #pragma unroll
            for (int r = 0; r < 4; r++)
                a[r] = *(const unsigned long long*)&As[ty * 4 + r][k];
            #pragma unroll
            for (int c = 0; c < 8; c++)
                b[c] = *(const unsigned long long*)&Bst[tx + 16 * c][k];
            #pragma unroll
            for (int r = 0; r < 4; r++)
                #pragma unroll
                for (int c = 0; c < 8; c++)
                    ffma2(acc[r][c], a[r], b[c]);
        }
        __syncthreads();
    }

    float* __restrict__ P = g_Tp[split];
    #pragma unroll
    for (int r = 0; r < 4; r++)
        #pragma unroll
        for (int c = 0; c < 8; c++)
            P[(size_t)(rb + ty * 4 + r) * RANK + tx + 16 * c] =
                f2lo(acc[r][c]) + f2hi(acc[r][c]);
}

// ---------------------------------------------------------------------------
// Kernel 2: combine K-split partials -> g_T, and per-row squared norms.
// 131072 float4 total; 512 blocks x 256 threads; one warp == one row.
// ---------------------------------------------------------------------------
__global__ void __launch_bounds__(256) combine_kernel()
{
    int idx = blockIdx.x * 256 + threadIdx.x;      // float4 index
    const float4* p0 = (const float4*)g_Tp[0];
    const float4* p1 = (const float4*)g_Tp[1];
    const float4* p2 = (const float4*)g_Tp[2];
    const float4* p3 = (const float4*)g_Tp[3];
    float4 a = p0[idx], b = p1[idx], c = p2[idx], d = p3[idx];
    float4 v;
    v.x = a.x + b.x + c.x + d.x;
    v.y = a.y + b.y + c.y + d.y;
    v.z = a.z + b.z + c.z + d.z;
    v.w = a.w + b.w + c.w + d.w;
    ((float4*)g_T)[idx] = v;

    float sq = v.x * v.x + v.y * v.y + v.z * v.z + v.w * v.w;
    #pragma unroll
    for (int off = 16; off > 0; off >>= 1)
        sq += __shfl_down_sync(0xffffffffu, sq, off);
    if ((threadIdx.x & 31) == 0)
        g_norm[idx >> 5] = sq;                     // 32 float4 per row
}

// ---------------------------------------------------------------------------
// Kernel 3: Gram-trick pairwise distances with triangular compute + mirror.
// out[b,i,j] = n[i] + n[j] - 2 * dot(T[i], T[j]); 64x64 tiles, FFMA2 k-paired.
// Grid (8,8,8); blocks with bj > bi exit (covered by mirror).
// ---------------------------------------------------------------------------
__global__ void __launch_bounds__(256) pdist_kernel(float* __restrict__ out)
{
    const int bj = blockIdx.x;
    const int bi = blockIdx.y;
    if (bj > bi) return;
    const int b  = blockIdx.z;
    const int i0 = bi * 64;
    const int j0 = bj * 64;

    __shared__ __align__(16) float Ti[64][68];   // stride 272B: 16B-mult
    __shared__ __align__(16) float Tj[64][68];

    const int tid = threadIdx.x;
    const int tx  = tid & 15;
    const int ty  = tid >> 4;

    const float* __restrict__ Tb = g_T + (size_t)b * SEQ * RANK;

    unsigned long long acc[4][4];
    #pragma unroll
    for (int r = 0; r < 4; r++)
        #pragma unroll
        for (int c = 0; c < 4; c++) acc[r][c] = 0ull;

    #pragma unroll
    for (int kc = 0; kc < RANK; kc += 64) {
        // Load 64x64 chunks of Ti and Tj: 1024 float4 each, 4/thread
        #pragma unroll
        for (int t = 0; t < 4; t++) {
            int idx = tid + t * 256;
            int r   = idx >> 4;
            int k4  = idx & 15;
            float4 v = *(const float4*)&Tb[(size_t)(i0 + r) * RANK + kc + k4 * 4];
            *(float4*)&Ti[r][k4 * 4] = v;
            float4 w = *(const float4*)&Tb[(size_t)(j0 + r) * RANK + kc + k4 * 4];
            *(float4*)&Tj[r][k4 * 4] = w;
        }
        __syncthreads();

        #pragma unroll
        for (int k = 0; k < 64; k += 2) {
            unsigned long long a[4], bv[4];
            #pragma unroll
            for (int r = 0; r < 4; r++)
                a[r] = *(const unsigned long long*)&Ti[ty * 4 + r][k];
            #pragma unroll
            for (int c = 0; c < 4; c++)
                bv[c] = *(const unsigned long long*)&Tj[tx + 16 * c][k];
            #pragma unroll
            for (int r = 0; r < 4; r++)
                #pragma unroll
                for (int c = 0; c < 4; c++)
                    ffma2(acc[r][c], a[r], bv[c]);
        }
        __syncthreads();
    }

    // Epilogue: d = n[i] + n[j] - 2*dot
    const float* __restrict__ nb = g_norm + (size_t)b * SEQ;
    float ni[4], nj[4], d[4][4];
    #pragma unroll
    for (int r = 0; r < 4; r++) ni[r] = nb[i0 + ty * 4 + r];
    #pragma unroll
    for (int c = 0; c < 4; c++) nj[c] = nb[j0 + tx + 16 * c];

    float* __restrict__ ob = out + (size_t)b * SEQ * SEQ;
    #pragma unroll
    for (int r = 0; r < 4; r++) {
        #pragma unroll
        for (int c = 0; c < 4; c++) {
            float dot = f2lo(acc[r][c]) + f2hi(acc[r][c]);
            float v = ni[r] + nj[c] - 2.0f * dot;
            if (bi == bj && (ty * 4 + r) == (tx + 16 * c)) v = 0.0f;  // exact diag
            d[r][c] = v;
            ob[(size_t)(i0 + ty * 4 + r) * SEQ + j0 + tx + 16 * c] = v;
        }
    }

    // Mirror to the upper-triangle tile via smem transpose (coalesced stores).
    if (bi != bj) {
        __syncthreads();          // done reading Ti for compute
        #pragma unroll
        for (int r = 0; r < 4; r++)
            #pragma unroll
            for (int c = 0; c < 4; c++)
                Ti[tx + 16 * c][ty * 4 + r] = d[r][c];   // Ts[jl][il]
        __syncthreads();
        #pragma unroll
        for (int r = 0; r < 4; r++)
            #pragma unroll
            for (int c = 0; c < 4; c++)
                ob[(size_t)(j0 + ty * 4 + r) * SEQ + i0 + tx + 16 * c] =
                    Ti[ty * 4 + r][tx + 16 * c];
    }
}

extern "C" void kernel_launch(void* const* d_in, const int* in_sizes, int n_in,
                              void* d_out, int out_size)
{
    const float* batch = (const float*)d_in[0];   // [8,512,1024]
    const float* proj  = (const float*)d_in[1];   // [1024,128]
    float* out = (float*)d_out;                   // [8,512,512]

    proj_gemm_kernel<<<dim3(KSPLIT, NROWS / 64), 256>>>(batch, proj);
    combine_kernel<<<NROWS * RANK / 4 / 256, 256>>>();
    pdist_kernel<<<dim3(8, 8, 8), 256>>>(out);
}

// round 3
// speedup vs baseline: 1.4997x; 1.1024x over previous
#include <cuda_runtime.h>

#define MDIM 1024
#define RANK 128
#define NBATCH 8
#define SEQ 512
#define NROWS (NBATCH * SEQ)          // 4096
#define KSPLIT 4
#define KS (MDIM / KSPLIT)            // 256

// Scratch (static __device__ globals; no allocations allowed).
__device__ float g_Tp[KSPLIT][NROWS * RANK];   // K-split partials, 8 MB
__device__ float g_T[NROWS * RANK];            // combined T, 2 MB
__device__ float g_norm[NROWS];                // row squared norms

// Packed fp32x2 FMA (Blackwell FFMA2; only reachable via PTX).
__device__ __forceinline__ void ffma2(unsigned long long& d,
                                      unsigned long long a,
                                      unsigned long long b) {
    asm("fma.rn.f32x2 %0, %1, %2, %0;" : "+l"(d) : "l"(a), "l"(b));
}
__device__ __forceinline__ float f2lo(unsigned long long x) {
    return __uint_as_float((unsigned)(x & 0xffffffffu));
}
__device__ __forceinline__ float f2hi(unsigned long long x) {
    return __uint_as_float((unsigned)(x >> 32));
}

// ---------------------------------------------------------------------------
// Kernel 1: K-split GEMM  g_Tp[s][:, nb] = A[:, sKS:(s+1)KS] @ B[sKS:, nb]
// BM=64, BN=64, BK=16, 256 threads, per-thread 4x4 FFMA2 (k-paired),
// register double-buffered global loads.
// Grid: (KSPLIT=4, 64 row-blocks, 2 n-blocks) = 512 blocks.
// ---------------------------------------------------------------------------
__global__ void __launch_bounds__(256, 3) proj_gemm_kernel(
    const float* __restrict__ A, const float* __restrict__ B)
{
    __shared__ __align__(16) float As[64][20];    // [m][k], stride 80B
    __shared__ __align__(16) float Bst[64][18];   // [n][k], stride 72B

    const int tid   = threadIdx.x;
    const int tx    = tid & 15;          // n
    const int ty    = tid >> 4;          // m
    const int split = blockIdx.x;
    const int rb    = blockIdx.y * 64;
    const int nb0   = blockIdx.z * 64;
    const int kbase = split * KS;

    // load-index precompute
    const int ar  = tid >> 2;            // A row 0..63
    const int ak4 = tid & 3;             // A float4-in-row
    const int bk  = tid >> 4;            // B k-row 0..15
    const int bn4 = tid & 15;            // B float4-in-row

    const float* __restrict__ Aptr = A + (size_t)(rb + ar) * MDIM + kbase + ak4 * 4;
    const float* __restrict__ Bptr = B + (size_t)(kbase + bk) * RANK + nb0 + bn4 * 4;

    unsigned long long acc[4][4];
    #pragma unroll
    for (int r = 0; r < 4; r++)
        #pragma unroll
        for (int c = 0; c < 4; c++) acc[r][c] = 0ull;

    float4 ra = *(const float4*)Aptr;
    float4 rb4 = *(const float4*)Bptr;

    for (int kk = 0; kk < KS; kk += 16) {
        // commit prefetched tiles to smem
        *(float4*)&As[ar][ak4 * 4] = ra;
        Bst[bn4 * 4 + 0][bk] = rb4.x;
        Bst[bn4 * 4 + 1][bk] = rb4.y;
        Bst[bn4 * 4 + 2][bk] = rb4.z;
        Bst[bn4 * 4 + 3][bk] = rb4.w;
        __syncthreads();

        // prefetch next chunk while computing
        if (kk + 16 < KS) {
            ra  = *(const float4*)(Aptr + kk + 16);
            rb4 = *(const float4*)(Bptr + (size_t)(kk + 16) * RANK);
        }

        #pragma unroll
        for (int k = 0; k < 16; k += 2) {
            unsigned long long a[4], b[4];
            #pragma unroll
            for (int r = 0; r < 4; r++)
                a[r] = *(const unsigned long long*)&As[ty * 4 + r][k];
            #pragma unroll
            for (int c = 0; c < 4; c++)
                b[c] = *(const unsigned long long*)&Bst[tx + 16 * c][k];
            #pragma unroll
            for (int r = 0; r < 4; r++)
                #pragma unroll
                for (int c = 0; c < 4; c++)
                    ffma2(acc[r][c], a[r], b[c]);
        }
        __syncthreads();
    }

    float* __restrict__ P = g_Tp[split];
    #pragma unroll
    for (int r = 0; r < 4; r++)
        #pragma unroll
        for (int c = 0; c < 4; c++)
            P[(size_t)(rb + ty * 4 + r) * RANK + nb0 + tx + 16 * c] =
                f2lo(acc[r][c]) + f2hi(acc[r][c]);
}

// ---------------------------------------------------------------------------
// Kernel 2: combine K-split partials -> g_T, and per-row squared norms.
// ---------------------------------------------------------------------------
__global__ void __launch_bounds__(256) combine_kernel()
{
    int idx = blockIdx.x * 256 + threadIdx.x;      // float4 index
    const float4* p0 = (const float4*)g_Tp[0];
    const float4* p1 = (const float4*)g_Tp[1];
    const float4* p2 = (const float4*)g_Tp[2];
    const float4* p3 = (const float4*)g_Tp[3];
    float4 a = p0[idx], b = p1[idx], c = p2[idx], d = p3[idx];
    float4 v;
    v.x = a.x + b.x + c.x + d.x;
    v.y = a.y + b.y + c.y + d.y;
    v.z = a.z + b.z + c.z + d.z;
    v.w = a.w + b.w + c.w + d.w;
    ((float4*)g_T)[idx] = v;

    float sq = v.x * v.x + v.y * v.y + v.z * v.z + v.w * v.w;
    #pragma unroll
    for (int off = 16; off > 0; off >>= 1)
        sq += __shfl_down_sync(0xffffffffu, sq, off);
    if ((threadIdx.x & 31) == 0)
        g_norm[idx >> 5] = sq;                     // 32 float4 per row
}

// ---------------------------------------------------------------------------
// Kernel 3: Gram-trick pairwise distances, triangular compute + mirror.
// ---------------------------------------------------------------------------
__global__ void __launch_bounds__(256) pdist_kernel(float* __restrict__ out)
{
    const int bj = blockIdx.x;
    const int bi = blockIdx.y;
    if (bj > bi) return;
    const int b  = blockIdx.z;
    const int i0 = bi * 64;
    const int j0 = bj * 64;

    __shared__ __align__(16) float Ti[64][68];
    __shared__ __align__(16) float Tj[64][68];

    const int tid = threadIdx.x;
    const int tx  = tid & 15;
    const int ty  = tid >> 4;

    const float* __restrict__ Tb = g_T + (size_t)b * SEQ * RANK;

    unsigned long long acc[4][4];
    #pragma unroll
    for (int r = 0; r < 4; r++)
        #pragma unroll
        for (int c = 0; c < 4; c++) acc[r][c] = 0ull;

    #pragma unroll
    for (int kc = 0; kc < RANK; kc += 64) {
        #pragma unroll
        for (int t = 0; t < 4; t++) {
            int idx = tid + t * 256;
            int r   = idx >> 4;
            int k4  = idx & 15;
            float4 v = *(const float4*)&Tb[(size_t)(i0 + r) * RANK + kc + k4 * 4];
            *(float4*)&Ti[r][k4 * 4] = v;
            float4 w = *(const float4*)&Tb[(size_t)(j0 + r) * RANK + kc + k4 * 4];
            *(float4*)&Tj[r][k4 * 4] = w;
        }
        __syncthreads();

        #pragma unroll
        for (int k = 0; k < 64; k += 2) {
            unsigned long long a[4], bv[4];
            #pragma unroll
            for (int r = 0; r < 4; r++)
                a[r] = *(const unsigned long long*)&Ti[ty * 4 + r][k];
            #pragma unroll
            for (int c = 0; c < 4; c++)
                bv[c] = *(const unsigned long long*)&Tj[tx + 16 * c][k];
            #pragma unroll
            for (int r = 0; r < 4; r++)
                #pragma unroll
                for (int c = 0; c < 4; c++)
                    ffma2(acc[r][c], a[r], bv[c]);
        }
        __syncthreads();
    }

    const float* __restrict__ nb = g_norm + (size_t)b * SEQ;
    float ni[4], nj[4], d[4][4];
    #pragma unroll
    for (int r = 0; r < 4; r++) ni[r] = nb[i0 + ty * 4 + r];
    #pragma unroll
    for (int c = 0; c < 4; c++) nj[c] = nb[j0 + tx + 16 * c];

    float* __restrict__ ob = out + (size_t)b * SEQ * SEQ;
    #pragma unroll
    for (int r = 0; r < 4; r++) {
        #pragma unroll
        for (int c = 0; c < 4; c++) {
            float dot = f2lo(acc[r][c]) + f2hi(acc[r][c]);
            float v = ni[r] + nj[c] - 2.0f * dot;
            if (bi == bj && (ty * 4 + r) == (tx + 16 * c)) v = 0.0f;
            d[r][c] = v;
            ob[(size_t)(i0 + ty * 4 + r) * SEQ + j0 + tx + 16 * c] = v;
        }
    }

    if (bi != bj) {
        __syncthreads();
        #pragma unroll
        for (int r = 0; r < 4; r++)
            #pragma unroll
            for (int c = 0; c < 4; c++)
                Ti[tx + 16 * c][ty * 4 + r] = d[r][c];
        __syncthreads();
        #pragma unroll
        for (int r = 0; r < 4; r++)
            #pragma unroll
            for (int c = 0; c < 4; c++)
                ob[(size_t)(j0 + ty * 4 + r) * SEQ + i0 + tx + 16 * c] =
                    Ti[ty * 4 + r][tx + 16 * c];
    }
}

extern "C" void kernel_launch(void* const* d_in, const int* in_sizes, int n_in,
                              void* d_out, int out_size)
{
    const float* batch = (const float*)d_in[0];   // [8,512,1024]
    const float* proj  = (const float*)d_in[1];   // [1024,128]
    float* out = (float*)d_out;                   // [8,512,512]

    proj_gemm_kernel<<<dim3(KSPLIT, NROWS / 64, 2), 256>>>(batch, proj);
    combine_kernel<<<NROWS * RANK / 4 / 256, 256>>>();
    pdist_kernel<<<dim3(8, 8, 8), 256>>>(out);
}

// round 5
// speedup vs baseline: 2.4282x; 1.6191x over previous
#include <cuda_runtime.h>
#include <cuda_bf16.h>
#include <cstdint>

#define MDIM 1024
#define RANK 128
#define NBATCH 8
#define SEQ 512
#define NROWS (NBATCH * SEQ)          // 4096
#define KSPLIT 4
#define KS (MDIM / KSPLIT)            // 256
#define KC 64                         // k per smem chunk
#define CHUNKS (KS / KC)              // 4

// Scratch (static __device__ globals; no allocations allowed).
__device__ float g_Tp[KSPLIT][NROWS * RANK];        // K-split partials, 8 MB
__device__ float g_T[NROWS * RANK];                 // combined T, 2 MB
__device__ float g_norm[NROWS];                     // row squared norms
__device__ __nv_bfloat16 g_Bhi[RANK * MDIM];        // B^T hi: [n][k]
__device__ __nv_bfloat16 g_Blo[RANK * MDIM];        // B^T lo: [n][k]

// ---------------- helpers ----------------
__device__ __forceinline__ uint32_t sm2u32(const void* p) {
    uint32_t a;
    asm("{ .reg .u64 t; cvta.to.shared.u64 t, %1; cvt.u32.u64 %0, t; }"
        : "=r"(a) : "l"(p));
    return a;
}
#define LDMX4(r, addr) \
    asm volatile("ldmatrix.sync.aligned.m8n8.x4.shared.b16 {%0,%1,%2,%3}, [%4];" \
        : "=r"((r)[0]), "=r"((r)[1]), "=r"((r)[2]), "=r"((r)[3]) : "r"(addr))

__device__ __forceinline__ void mma_bf16(float* c, const uint32_t* a,
                                         uint32_t b0, uint32_t b1) {
    asm volatile(
        "mma.sync.aligned.m16n8k16.row.col.f32.bf16.bf16.f32 "
        "{%0,%1,%2,%3}, {%4,%5,%6,%7}, {%8,%9}, {%0,%1,%2,%3};"
        : "+f"(c[0]), "+f"(c[1]), "+f"(c[2]), "+f"(c[3])
        : "r"(a[0]), "r"(a[1]), "r"(a[2]), "r"(a[3]), "r"(b0), "r"(b1));
}

// Packed fp32x2 FMA (for pdist).
__device__ __forceinline__ void ffma2(unsigned long long& d,
                                      unsigned long long a,
                                      unsigned long long b) {
    asm("fma.rn.f32x2 %0, %1, %2, %0;" : "+l"(d) : "l"(a), "l"(b));
}
__device__ __forceinline__ float f2lo(unsigned long long x) {
    return __uint_as_float((unsigned)(x & 0xffffffffu));
}
__device__ __forceinline__ float f2hi(unsigned long long x) {
    return __uint_as_float((unsigned)(x >> 32));
}

// ---------------------------------------------------------------------------
// Kernel 0: transpose+split proj [1024,128] fp32 -> g_Bhi/g_Blo [128][1024] bf16
// ---------------------------------------------------------------------------
__global__ void convertB_kernel(const float* __restrict__ proj)
{
    __shared__ float tile[32][33];
    const int tx = threadIdx.x, ty = threadIdx.y;      // (32,8)
    const int k0 = blockIdx.x * 32, n0 = blockIdx.y * 32;
    #pragma unroll
    for (int i = 0; i < 4; i++)
        tile[ty + 8 * i][tx] = proj[(size_t)(k0 + ty + 8 * i) * RANK + n0 + tx];
    __syncthreads();
    #pragma unroll
    for (int i = 0; i < 4; i++) {
        int n = n0 + ty + 8 * i, k = k0 + tx;
        float v = tile[tx][ty + 8 * i];
        __nv_bfloat16 h = __float2bfloat16(v);
        __nv_bfloat16 l = __float2bfloat16(v - __bfloat162float(h));
        g_Bhi[(size_t)n * MDIM + k] = h;
        g_Blo[(size_t)n * MDIM + k] = l;
    }
}

// ---------------------------------------------------------------------------
// Kernel 1: mma.sync bf16-split GEMM. grid (KSPLIT, 64), 256 thr.
// CTA: M=64 rows, N=128, K=KS(256) in 4 chunks of 64.
// 8 warps = 4(m)x2(n); warp tile 16x64. acc(f32) += Ahi*Bhi + Ahi*Blo + Alo*Bhi.
// smem rows padded to 144B (A: 64 rows, Bhi/Blo: 128 rows each).
// ---------------------------------------------------------------------------
#define AHI_OFF 0
#define ALO_OFF 9216
#define BHI_OFF 18432
#define BLO_OFF 36864
#define SMEM_BYTES 55296

__global__ void __launch_bounds__(256) mma_gemm_kernel(const float* __restrict__ A)
{
    extern __shared__ char dsm[];
    const int tid  = threadIdx.x;
    const int wid  = tid >> 5, lane = tid & 31;
    const int split = blockIdx.x;
    const int mb    = blockIdx.y * 64;
    const int kbase = split * KS;

    const int warp_m = (wid & 3) * 16;
    const int warp_n = (wid >> 2) * 64;

    const uint32_t smem = sm2u32(dsm);
    // ldmatrix lane addresses (bytes)
    const uint32_t a_off = (uint32_t)(warp_m + (lane & 15)) * 144 + (lane >> 4) * 16;
    const uint32_t aaddr_hi = smem + AHI_OFF + a_off;
    const uint32_t aaddr_lo = smem + ALO_OFF + a_off;
    const uint32_t b_noff = ((lane >> 3) & 1) * 8 + (lane & 7);
    const uint32_t b_off  = (uint32_t)(warp_n + b_noff) * 144 + (lane >> 4) * 16;
    const uint32_t baddr_hi = smem + BHI_OFF + b_off;
    const uint32_t baddr_lo = smem + BLO_OFF + b_off;

    float acc[8][4];
    #pragma unroll
    for (int i = 0; i < 8; i++)
        #pragma unroll
        for (int j = 0; j < 4; j++) acc[i][j] = 0.0f;

    for (int c = 0; c < CHUNKS; c++) {
        if (c) __syncthreads();

        // A chunk [64][64] fp32 -> bf16 hi/lo into smem
        #pragma unroll
        for (int t = 0; t < 4; t++) {
            int idx = tid + t * 256;
            int r = idx >> 4, k4 = idx & 15;
            float4 v = *(const float4*)&A[(size_t)(mb + r) * MDIM + kbase + c * KC + k4 * 4];
            __nv_bfloat16 h0 = __float2bfloat16(v.x);
            __nv_bfloat16 h1 = __float2bfloat16(v.y);
            __nv_bfloat16 h2 = __float2bfloat16(v.z);
            __nv_bfloat16 h3 = __float2bfloat16(v.w);
            union { __nv_bfloat162 b2[2]; unsigned long long u; } ph, pl;
            ph.b2[0] = __nv_bfloat162(h0, h1);
            ph.b2[1] = __nv_bfloat162(h2, h3);
            pl.b2[0] = __nv_bfloat162(__float2bfloat16(v.x - __bfloat162float(h0)),
                                      __float2bfloat16(v.y - __bfloat162float(h1)));
            pl.b2[1] = __nv_bfloat162(__float2bfloat16(v.z - __bfloat162float(h2)),
                                      __float2bfloat16(v.w - __bfloat162float(h3)));
            *(unsigned long long*)(dsm + AHI_OFF + r * 144 + k4 * 8) = ph.u;
            *(unsigned long long*)(dsm + ALO_OFF + r * 144 + k4 * 8) = pl.u;
        }
        // B chunk [128][64] bf16 hi/lo (preconverted) into smem
        #pragma unroll
        for (int t = 0; t < 4; t++) {
            int idx = tid + t * 256;
            int n = idx >> 3, g = idx & 7;
            size_t src = (size_t)n * MDIM + kbase + c * KC + g * 8;
            *(uint4*)(dsm + BHI_OFF + n * 144 + g * 16) = *(const uint4*)&g_Bhi[src];
            *(uint4*)(dsm + BLO_OFF + n * 144 + g * 16) = *(const uint4*)&g_Blo[src];
        }
        __syncthreads();

        #pragma unroll
        for (int kk = 0; kk < 4; kk++) {
            uint32_t ah[4], al[4];
            LDMX4(ah, aaddr_hi + kk * 32);
            LDMX4(al, aaddr_lo + kk * 32);
            #pragma unroll
            for (int nn = 0; nn < 4; nn++) {
                uint32_t bh[4], bl[4];
                LDMX4(bh, baddr_hi + nn * 16 * 144 + kk * 32);
                LDMX4(bl, baddr_lo + nn * 16 * 144 + kk * 32);
                float* c0 = acc[nn * 2];
                float* c1 = acc[nn * 2 + 1];
                mma_bf16(c0, ah, bh[0], bh[2]);
                mma_bf16(c0, ah, bl[0], bl[2]);
                mma_bf16(c0, al, bh[0], bh[2]);
                mma_bf16(c1, ah, bh[1], bh[3]);
                mma_bf16(c1, ah, bl[1], bl[3]);
                mma_bf16(c1, al, bh[1], bh[3]);
            }
        }
    }

    // Epilogue: fragment layout c0,c1 at (m = t/4, n = frag*8 + (t%4)*2), c2,c3 at m+8.
    float* __restrict__ P = g_Tp[split];
    const int m0 = mb + warp_m + (lane >> 2);
    #pragma unroll
    for (int ch = 0; ch < 8; ch++) {
        int n = warp_n + ch * 8 + (lane & 3) * 2;
        float2 lo = make_float2(acc[ch][0], acc[ch][1]);
        float2 hi = make_float2(acc[ch][2], acc[ch][3]);
        *(float2*)&P[(size_t)m0 * RANK + n] = lo;
        *(float2*)&P[(size_t)(m0 + 8) * RANK + n] = hi;
    }
}

// ---------------------------------------------------------------------------
// Kernel 2: combine K-split partials -> g_T, and per-row squared norms.
// ---------------------------------------------------------------------------
__global__ void __launch_bounds__(256) combine_kernel()
{
    int idx = blockIdx.x * 256 + threadIdx.x;      // float4 index
    const float4* p0 = (const float4*)g_Tp[0];
    const float4* p1 = (const float4*)g_Tp[1];
    const float4* p2 = (const float4*)g_Tp[2];
    const float4* p3 = (const float4*)g_Tp[3];
    float4 a = p0[idx], b = p1[idx], c = p2[idx], d = p3[idx];
    float4 v;
    v.x = a.x + b.x + c.x + d.x;
    v.y = a.y + b.y + c.y + d.y;
    v.z = a.z + b.z + c.z + d.z;
    v.w = a.w + b.w + c.w + d.w;
    ((float4*)g_T)[idx] = v;

    float sq = v.x * v.x + v.y * v.y + v.z * v.z + v.w * v.w;
    #pragma unroll
    for (int off = 16; off > 0; off >>= 1)
        sq += __shfl_down_sync(0xffffffffu, sq, off);
    if ((threadIdx.x & 31) == 0)
        g_norm[idx >> 5] = sq;                     // 32 float4 per row
}

// ---------------------------------------------------------------------------
// Kernel 3: Gram-trick pairwise distances, triangular compute + mirror.
// ---------------------------------------------------------------------------
__global__ void __launch_bounds__(256) pdist_kernel(float* __restrict__ out)
{
    const int bj = blockIdx.x;
    const int bi = blockIdx.y;
    if (bj > bi) return;
    const int b  = blockIdx.z;
    const int i0 = bi * 64;
    const int j0 = bj * 64;

    __shared__ __align__(16) float Ti[64][68];
    __shared__ __align__(16) float Tj[64][68];

    const int tid = threadIdx.x;
    const int tx  = tid & 15;
    const int ty  = tid >> 4;

    const float* __restrict__ Tb = g_T + (size_t)b * SEQ * RANK;

    unsigned long long acc[4][4];
    #pragma unroll
    for (int r = 0; r < 4; r++)
        #pragma unroll
        for (int c = 0; c < 4; c++) acc[r][c] = 0ull;

    #pragma unroll
    for (int kc = 0; kc < RANK; kc += 64) {
        #pragma unroll
        for (int t = 0; t < 4; t++) {
            int idx = tid + t * 256;
            int r   = idx >> 4;
            int k4  = idx & 15;
            float4 v = *(const float4*)&Tb[(size_t)(i0 + r) * RANK + kc + k4 * 4];
            *(float4*)&Ti[r][k4 * 4] = v;
            float4 w = *(const float4*)&Tb[(size_t)(j0 + r) * RANK + kc + k4 * 4];
            *(float4*)&Tj[r][k4 * 4] = w;
        }
        __syncthreads();

        #pragma unroll
        for (int k = 0; k < 64; k += 2) {
            unsigned long long a[4], bv[4];
            #pragma unroll
            for (int r = 0; r < 4; r++)
                a[r] = *(const unsigned long long*)&Ti[ty * 4 + r][k];
            #pragma unroll
            for (int c = 0; c < 4; c++)
                bv[c] = *(const unsigned long long*)&Tj[tx + 16 * c][k];
            #pragma unroll
            for (int r = 0; r < 4; r++)
                #pragma unroll
                for (int c = 0; c < 4; c++)
                    ffma2(acc[r][c], a[r], bv[c]);
        }
        __syncthreads();
    }

    const float* __restrict__ nb = g_norm + (size_t)b * SEQ;
    float ni[4], nj[4], d[4][4];
    #pragma unroll
    for (int r = 0; r < 4; r++) ni[r] = nb[i0 + ty * 4 + r];
    #pragma unroll
    for (int c = 0; c < 4; c++) nj[c] = nb[j0 + tx + 16 * c];

    float* __restrict__ ob = out + (size_t)b * SEQ * SEQ;
    #pragma unroll
    for (int r = 0; r < 4; r++) {
        #pragma unroll
        for (int c = 0; c < 4; c++) {
            float dot = f2lo(acc[r][c]) + f2hi(acc[r][c]);
            float v = ni[r] + nj[c] - 2.0f * dot;
            if (bi == bj && (ty * 4 + r) == (tx + 16 * c)) v = 0.0f;
            d[r][c] = v;
            ob[(size_t)(i0 + ty * 4 + r) * SEQ + j0 + tx + 16 * c] = v;
        }
    }

    if (bi != bj) {
        __syncthreads();
        #pragma unroll
        for (int r = 0; r < 4; r++)
            #pragma unroll
            for (int c = 0; c < 4; c++)
                Ti[tx + 16 * c][ty * 4 + r] = d[r][c];
        __syncthreads();
        #pragma unroll
        for (int r = 0; r < 4; r++)
            #pragma unroll
            for (int c = 0; c < 4; c++)
                ob[(size_t)(j0 + ty * 4 + r) * SEQ + i0 + tx + 16 * c] =
                    Ti[ty * 4 + r][tx + 16 * c];
    }
}

extern "C" void kernel_launch(void* const* d_in, const int* in_sizes, int n_in,
                              void* d_out, int out_size)
{
    const float* batch = (const float*)d_in[0];   // [8,512,1024]
    const float* proj  = (const float*)d_in[1];   // [1024,128]
    float* out = (float*)d_out;                   // [8,512,512]

    // Idempotent; first call happens on the correctness run (outside capture).
    cudaFuncSetAttribute(mma_gemm_kernel,
                         cudaFuncAttributeMaxDynamicSharedMemorySize, SMEM_BYTES);

    convertB_kernel<<<dim3(MDIM / 32, RANK / 32), dim3(32, 8)>>>(proj);
    mma_gemm_kernel<<<dim3(KSPLIT, NROWS / 64), 256, SMEM_BYTES>>>(batch);
    combine_kernel<<<NROWS * RANK / 4 / 256, 256>>>();
    pdist_kernel<<<dim3(8, 8, 8), 256>>>(out);
}

// round 6
// speedup vs baseline: 2.5589x; 1.0539x over previous
#include <cuda_runtime.h>
#include <cuda_bf16.h>
#include <cstdint>

#define MDIM 1024
#define RANK 128
#define NBATCH 8
#define SEQ 512
#define NROWS (NBATCH * SEQ)          // 4096
#define KSPLIT 4
#define KS (MDIM / KSPLIT)            // 256
#define KC 64                         // k per smem chunk (gemm)
#define CHUNKS (KS / KC)              // 4

// Scratch (static __device__ globals; no allocations allowed).
__device__ float g_Tp[KSPLIT][NROWS * RANK];        // K-split partials, 8 MB
__device__ float g_norm[NROWS];                     // row squared norms
__device__ __nv_bfloat16 g_Bhi[RANK * MDIM];        // B^T hi: [n][k]
__device__ __nv_bfloat16 g_Blo[RANK * MDIM];        // B^T lo: [n][k]
__device__ __nv_bfloat16 g_Thi[NROWS * RANK];       // T hi: [row][k]
__device__ __nv_bfloat16 g_Tlo[NROWS * RANK];       // T lo: [row][k]

// ---------------- helpers ----------------
__device__ __forceinline__ uint32_t sm2u32(const void* p) {
    uint32_t a;
    asm("{ .reg .u64 t; cvta.to.shared.u64 t, %1; cvt.u32.u64 %0, t; }"
        : "=r"(a) : "l"(p));
    return a;
}
#define LDMX4(r, addr) \
    asm volatile("ldmatrix.sync.aligned.m8n8.x4.shared.b16 {%0,%1,%2,%3}, [%4];" \
        : "=r"((r)[0]), "=r"((r)[1]), "=r"((r)[2]), "=r"((r)[3]) : "r"(addr))

__device__ __forceinline__ void mma_bf16(float* c, const uint32_t* a,
                                         uint32_t b0, uint32_t b1) {
    asm volatile(
        "mma.sync.aligned.m16n8k16.row.col.f32.bf16.bf16.f32 "
        "{%0,%1,%2,%3}, {%4,%5,%6,%7}, {%8,%9}, {%0,%1,%2,%3};"
        : "+f"(c[0]), "+f"(c[1]), "+f"(c[2]), "+f"(c[3])
        : "r"(a[0]), "r"(a[1]), "r"(a[2]), "r"(a[3]), "r"(b0), "r"(b1));
}

// ---------------------------------------------------------------------------
// Kernel 0: transpose+split proj [1024,128] fp32 -> g_Bhi/g_Blo [128][1024] bf16
// ---------------------------------------------------------------------------
__global__ void convertB_kernel(const float* __restrict__ proj)
{
    __shared__ float tile[32][33];
    const int tx = threadIdx.x, ty = threadIdx.y;      // (32,8)
    const int k0 = blockIdx.x * 32, n0 = blockIdx.y * 32;
    #pragma unroll
    for (int i = 0; i < 4; i++)
        tile[ty + 8 * i][tx] = proj[(size_t)(k0 + ty + 8 * i) * RANK + n0 + tx];
    __syncthreads();
    #pragma unroll
    for (int i = 0; i < 4; i++) {
        int n = n0 + ty + 8 * i, k = k0 + tx;
        float v = tile[tx][ty + 8 * i];
        __nv_bfloat16 h = __float2bfloat16(v);
        __nv_bfloat16 l = __float2bfloat16(v - __bfloat162float(h));
        g_Bhi[(size_t)n * MDIM + k] = h;
        g_Blo[(size_t)n * MDIM + k] = l;
    }
}

// ---------------------------------------------------------------------------
// Kernel 1: mma.sync bf16-split GEMM. grid (KSPLIT, 64), 256 thr.
// CTA: M=64 rows, N=128, K=KS(256) in 4 chunks of 64.
// 8 warps = 4(m)x2(n); warp tile 16x64. acc(f32) += Ahi*Bhi + Ahi*Blo + Alo*Bhi.
// smem rows padded to 144B.
// ---------------------------------------------------------------------------
#define AHI_OFF 0
#define ALO_OFF 9216
#define BHI_OFF 18432
#define BLO_OFF 36864
#define SMEM_BYTES 55296

__global__ void __launch_bounds__(256) mma_gemm_kernel(const float* __restrict__ A)
{
    extern __shared__ char dsm[];
    const int tid  = threadIdx.x;
    const int wid  = tid >> 5, lane = tid & 31;
    const int split = blockIdx.x;
    const int mb    = blockIdx.y * 64;
    const int kbase = split * KS;

    const int warp_m = (wid & 3) * 16;
    const int warp_n = (wid >> 2) * 64;

    const uint32_t smem = sm2u32(dsm);
    const uint32_t a_off = (uint32_t)(warp_m + (lane & 15)) * 144 + (lane >> 4) * 16;
    const uint32_t aaddr_hi = smem + AHI_OFF + a_off;
    const uint32_t aaddr_lo = smem + ALO_OFF + a_off;
    const uint32_t b_noff = ((lane >> 3) & 1) * 8 + (lane & 7);
    const uint32_t b_off  = (uint32_t)(warp_n + b_noff) * 144 + (lane >> 4) * 16;
    const uint32_t baddr_hi = smem + BHI_OFF + b_off;
    const uint32_t baddr_lo = smem + BLO_OFF + b_off;

    float acc[8][4];
    #pragma unroll
    for (int i = 0; i < 8; i++)
        #pragma unroll
        for (int j = 0; j < 4; j++) acc[i][j] = 0.0f;

    for (int c = 0; c < CHUNKS; c++) {
        if (c) __syncthreads();

        #pragma unroll
        for (int t = 0; t < 4; t++) {
            int idx = tid + t * 256;
            int r = idx >> 4, k4 = idx & 15;
            float4 v = *(const float4*)&A[(size_t)(mb + r) * MDIM + kbase + c * KC + k4 * 4];
            __nv_bfloat16 h0 = __float2bfloat16(v.x);
            __nv_bfloat16 h1 = __float2bfloat16(v.y);
            __nv_bfloat16 h2 = __float2bfloat16(v.z);
            __nv_bfloat16 h3 = __float2bfloat16(v.w);
            union { __nv_bfloat162 b2[2]; unsigned long long u; } ph, pl;
            ph.b2[0] = __nv_bfloat162(h0, h1);
            ph.b2[1] = __nv_bfloat162(h2, h3);
            pl.b2[0] = __nv_bfloat162(__float2bfloat16(v.x - __bfloat162float(h0)),
                                      __float2bfloat16(v.y - __bfloat162float(h1)));
            pl.b2[1] = __nv_bfloat162(__float2bfloat16(v.z - __bfloat162float(h2)),
                                      __float2bfloat16(v.w - __bfloat162float(h3)));
            *(unsigned long long*)(dsm + AHI_OFF + r * 144 + k4 * 8) = ph.u;
            *(unsigned long long*)(dsm + ALO_OFF + r * 144 + k4 * 8) = pl.u;
        }
        #pragma unroll
        for (int t = 0; t < 4; t++) {
            int idx = tid + t * 256;
            int n = idx >> 3, g = idx & 7;
            size_t src = (size_t)n * MDIM + kbase + c * KC + g * 8;
            *(uint4*)(dsm + BHI_OFF + n * 144 + g * 16) = *(const uint4*)&g_Bhi[src];
            *(uint4*)(dsm + BLO_OFF + n * 144 + g * 16) = *(const uint4*)&g_Blo[src];
        }
        __syncthreads();

        #pragma unroll
        for (int kk = 0; kk < 4; kk++) {
            uint32_t ah[4], al[4];
            LDMX4(ah, aaddr_hi + kk * 32);
            LDMX4(al, aaddr_lo + kk * 32);
            #pragma unroll
            for (int nn = 0; nn < 4; nn++) {
                uint32_t bh[4], bl[4];
                LDMX4(bh, baddr_hi + nn * 16 * 144 + kk * 32);
                LDMX4(bl, baddr_lo + nn * 16 * 144 + kk * 32);
                float* c0 = acc[nn * 2];
                float* c1 = acc[nn * 2 + 1];
                mma_bf16(c0, ah, bh[0], bh[2]);
                mma_bf16(c0, ah, bl[0], bl[2]);
                mma_bf16(c0, al, bh[0], bh[2]);
                mma_bf16(c1, ah, bh[1], bh[3]);
                mma_bf16(c1, ah, bl[1], bl[3]);
                mma_bf16(c1, al, bh[1], bh[3]);
            }
        }
    }

    float* __restrict__ P = g_Tp[split];
    const int m0 = mb + warp_m + (lane >> 2);
    #pragma unroll
    for (int ch = 0; ch < 8; ch++) {
        int n = warp_n + ch * 8 + (lane & 3) * 2;
        *(float2*)&P[(size_t)m0 * RANK + n] = make_float2(acc[ch][0], acc[ch][1]);
        *(float2*)&P[(size_t)(m0 + 8) * RANK + n] = make_float2(acc[ch][2], acc[ch][3]);
    }
}

// ---------------------------------------------------------------------------
// Kernel 2: combine K-split partials -> bf16 hi/lo T + per-row squared norms.
// ---------------------------------------------------------------------------
__global__ void __launch_bounds__(256) combine_kernel()
{
    int idx = blockIdx.x * 256 + threadIdx.x;      // float4 index
    const float4* p0 = (const float4*)g_Tp[0];
    const float4* p1 = (const float4*)g_Tp[1];
    const float4* p2 = (const float4*)g_Tp[2];
    const float4* p3 = (const float4*)g_Tp[3];
    float4 a = p0[idx], b = p1[idx], c = p2[idx], d = p3[idx];
    float4 v;
    v.x = a.x + b.x + c.x + d.x;
    v.y = a.y + b.y + c.y + d.y;
    v.z = a.z + b.z + c.z + d.z;
    v.w = a.w + b.w + c.w + d.w;

    __nv_bfloat16 h0 = __float2bfloat16(v.x);
    __nv_bfloat16 h1 = __float2bfloat16(v.y);
    __nv_bfloat16 h2 = __float2bfloat16(v.z);
    __nv_bfloat16 h3 = __float2bfloat16(v.w);
    union { __nv_bfloat162 b2[2]; uint2 u; } ph, pl;
    ph.b2[0] = __nv_bfloat162(h0, h1);
    ph.b2[1] = __nv_bfloat162(h2, h3);
    pl.b2[0] = __nv_bfloat162(__float2bfloat16(v.x - __bfloat162float(h0)),
                              __float2bfloat16(v.y - __bfloat162float(h1)));
    pl.b2[1] = __nv_bfloat162(__float2bfloat16(v.z - __bfloat162float(h2)),
                              __float2bfloat16(v.w - __bfloat162float(h3)));
    *(uint2*)&g_Thi[(size_t)idx * 4] = ph.u;
    *(uint2*)&g_Tlo[(size_t)idx * 4] = pl.u;

    float sq = v.x * v.x + v.y * v.y + v.z * v.z + v.w * v.w;
    #pragma unroll
    for (int off = 16; off > 0; off >>= 1)
        sq += __shfl_down_sync(0xffffffffu, sq, off);
    if ((threadIdx.x & 31) == 0)
        g_norm[idx >> 5] = sq;                     // 32 float4 per row
}

// ---------------------------------------------------------------------------
// Kernel 3: pdist via mma.sync bf16 hi/lo Gram.
// CTA: 128(i) x 128(j) tile, full K=128 in smem. grid (4,4,8), 256 thr.
// 8 warps = 4(m)x2(n); warp tile 32x64.
// d(i,j) = n_i + n_j - 2*(Ihi·Jhi + Ihi·Jlo + Ilo·Jhi); diag forced to 0.
// smem rows 272B (128 k * 2B + 16 pad); 272 % 128 = 16 -> ldmatrix conflict-free.
// ---------------------------------------------------------------------------
#define PD_IH 0
#define PD_IL 34816
#define PD_JH 69632
#define PD_JL 104448
#define PD_SMEM 139264
#define PD_STR 272

__global__ void __launch_bounds__(256) pdist_mma_kernel(float* __restrict__ out)
{
    extern __shared__ char dsm[];
    const int tid  = threadIdx.x;
    const int wid  = tid >> 5, lane = tid & 31;
    const int bj = blockIdx.x, bi = blockIdx.y, b = blockIdx.z;
    const int i0 = bi * 128, j0 = bj * 128;
    const bool diag = (bi == bj);

    const __nv_bfloat16* __restrict__ TH = g_Thi + (size_t)b * SEQ * RANK;
    const __nv_bfloat16* __restrict__ TL = g_Tlo + (size_t)b * SEQ * RANK;

    // Stage I (and J if off-diagonal): 128 rows x 128 k bf16, hi+lo.
    #pragma unroll
    for (int t = 0; t < 8; t++) {
        int idx = tid + t * 256;          // 0..2047
        int r = idx >> 4, g = idx & 15;
        size_t si = (size_t)(i0 + r) * RANK + g * 8;
        *(uint4*)(dsm + PD_IH + r * PD_STR + g * 16) = *(const uint4*)&TH[si];
        *(uint4*)(dsm + PD_IL + r * PD_STR + g * 16) = *(const uint4*)&TL[si];
        if (!diag) {
            size_t sj = (size_t)(j0 + r) * RANK + g * 8;
            *(uint4*)(dsm + PD_JH + r * PD_STR + g * 16) = *(const uint4*)&TH[sj];
            *(uint4*)(dsm + PD_JL + r * PD_STR + g * 16) = *(const uint4*)&TL[sj];
        }
    }
    __syncthreads();

    const int warp_m = (wid & 3) * 32;
    const int warp_n = (wid >> 2) * 64;
    const uint32_t smem = sm2u32(dsm);

    const uint32_t ia_off = (uint32_t)(warp_m + (lane & 15)) * PD_STR + (lane >> 4) * 16;
    const uint32_t iaddr_h = smem + PD_IH + ia_off;
    const uint32_t iaddr_l = smem + PD_IL + ia_off;
    const uint32_t j_noff = ((lane >> 3) & 1) * 8 + (lane & 7);
    const uint32_t ja_off = (uint32_t)(warp_n + j_noff) * PD_STR + (lane >> 4) * 16;
    const uint32_t jaddr_h = smem + (diag ? PD_IH : PD_JH) + ja_off;
    const uint32_t jaddr_l = smem + (diag ? PD_IL : PD_JL) + ja_off;

    float acc[2][8][4];
    #pragma unroll
    for (int mf = 0; mf < 2; mf++)
        #pragma unroll
        for (int i = 0; i < 8; i++)
            #pragma unroll
            for (int j = 0; j < 4; j++) acc[mf][i][j] = 0.0f;

    #pragma unroll
    for (int kk = 0; kk < 8; kk++) {
        uint32_t ih[2][4], il[2][4];
        LDMX4(ih[0], iaddr_h + kk * 32);
        LDMX4(ih[1], iaddr_h + 16 * PD_STR + kk * 32);
        LDMX4(il[0], iaddr_l + kk * 32);
        LDMX4(il[1], iaddr_l + 16 * PD_STR + kk * 32);
        #pragma unroll
        for (int nn = 0; nn < 4; nn++) {
            uint32_t jh[4], jl[4];
            LDMX4(jh, jaddr_h + nn * 16 * PD_STR + kk * 32);
            LDMX4(jl, jaddr_l + nn * 16 * PD_STR + kk * 32);
            #pragma unroll
            for (int mf = 0; mf < 2; mf++) {
                float* c0 = acc[mf][nn * 2];
                float* c1 = acc[mf][nn * 2 + 1];
                mma_bf16(c0, ih[mf], jh[0], jh[2]);
                mma_bf16(c0, ih[mf], jl[0], jl[2]);
                mma_bf16(c0, il[mf], jh[0], jh[2]);
                mma_bf16(c1, ih[mf], jh[1], jh[3]);
                mma_bf16(c1, ih[mf], jl[1], jl[3]);
                mma_bf16(c1, il[mf], jh[1], jh[3]);
            }
        }
    }

    // Epilogue: d = n_i + n_j - 2*dot; exact 0 on diagonal.
    const float* __restrict__ nb = g_norm + (size_t)b * SEQ;
    float* __restrict__ ob = out + (size_t)b * SEQ * SEQ;
    #pragma unroll
    for (int mf = 0; mf < 2; mf++) {
        int gi = i0 + warp_m + mf * 16 + (lane >> 2);
        float ni0 = nb[gi], ni1 = nb[gi + 8];
        #pragma unroll
        for (int ch = 0; ch < 8; ch++) {
            int gj = j0 + warp_n + ch * 8 + (lane & 3) * 2;
            float nj0 = nb[gj], nj1 = nb[gj + 1];
            float* a = acc[mf][ch];
            float v00 = ni0 + nj0 - 2.0f * a[0];
            float v01 = ni0 + nj1 - 2.0f * a[1];
            float v10 = ni1 + nj0 - 2.0f * a[2];
            float v11 = ni1 + nj1 - 2.0f * a[3];
            if (diag) {
                if (gi == gj) v00 = 0.0f;
                if (gi == gj + 1) v01 = 0.0f;
                if (gi + 8 == gj) v10 = 0.0f;
                if (gi + 8 == gj + 1) v11 = 0.0f;
            }
            *(float2*)&ob[(size_t)gi * SEQ + gj] = make_float2(v00, v01);
            *(float2*)&ob[(size_t)(gi + 8) * SEQ + gj] = make_float2(v10, v11);
        }
    }
}

extern "C" void kernel_launch(void* const* d_in, const int* in_sizes, int n_in,
                              void* d_out, int out_size)
{
    const float* batch = (const float*)d_in[0];   // [8,512,1024]
    const float* proj  = (const float*)d_in[1];   // [1024,128]
    float* out = (float*)d_out;                   // [8,512,512]

    // Idempotent; first call happens on the correctness run (outside capture).
    cudaFuncSetAttribute(mma_gemm_kernel,
                         cudaFuncAttributeMaxDynamicSharedMemorySize, SMEM_BYTES);
    cudaFuncSetAttribute(pdist_mma_kernel,
                         cudaFuncAttributeMaxDynamicSharedMemorySize, PD_SMEM);

    convertB_kernel<<<dim3(MDIM / 32, RANK / 32), dim3(32, 8)>>>(proj);
    mma_gemm_kernel<<<dim3(KSPLIT, NROWS / 64), 256, SMEM_BYTES>>>(batch);
    combine_kernel<<<NROWS * RANK / 4 / 256, 256>>>();
    pdist_mma_kernel<<<dim3(4, 4, 8), 256, PD_SMEM>>>(out);
}

// round 7
// speedup vs baseline: 2.5826x; 1.0092x over previous
#include <cuda_runtime.h>
#include <cuda_bf16.h>
#include <cstdint>

#define MDIM 1024
#define RANK 128
#define NBATCH 8
#define SEQ 512
#define NROWS (NBATCH * SEQ)          // 4096
#define KSPLIT 4
#define KS (MDIM / KSPLIT)            // 256
#define KC 64                         // k per smem chunk (gemm)
#define CHUNKS (KS / KC)              // 4

// Scratch (static __device__ globals; no allocations allowed).
__device__ float g_Tp[KSPLIT][NROWS * RANK];        // K-split partials, 8 MB
__device__ float g_norm[NROWS];                     // row squared norms
__device__ __nv_bfloat16 g_Bhi[RANK * MDIM];        // B^T hi: [n][k]
__device__ __nv_bfloat16 g_Blo[RANK * MDIM];        // B^T lo: [n][k]
__device__ __nv_bfloat16 g_Thi[NROWS * RANK];       // T hi: [row][k]
__device__ __nv_bfloat16 g_Tlo[NROWS * RANK];       // T lo: [row][k]

// ---------------- helpers ----------------
__device__ __forceinline__ uint32_t sm2u32(const void* p) {
    uint32_t a;
    asm("{ .reg .u64 t; cvta.to.shared.u64 t, %1; cvt.u32.u64 %0, t; }"
        : "=r"(a) : "l"(p));
    return a;
}
#define LDMX4(r, addr) \
    asm volatile("ldmatrix.sync.aligned.m8n8.x4.shared.b16 {%0,%1,%2,%3}, [%4];" \
        : "=r"((r)[0]), "=r"((r)[1]), "=r"((r)[2]), "=r"((r)[3]) : "r"(addr))

__device__ __forceinline__ void mma_bf16(float* c, const uint32_t* a,
                                         uint32_t b0, uint32_t b1) {
    asm volatile(
        "mma.sync.aligned.m16n8k16.row.col.f32.bf16.bf16.f32 "
        "{%0,%1,%2,%3}, {%4,%5,%6,%7}, {%8,%9}, {%0,%1,%2,%3};"
        : "+f"(c[0]), "+f"(c[1]), "+f"(c[2]), "+f"(c[3])
        : "r"(a[0]), "r"(a[1]), "r"(a[2]), "r"(a[3]), "r"(b0), "r"(b1));
}

// ---------------------------------------------------------------------------
// Kernel 0: transpose+split proj [1024,128] fp32 -> g_Bhi/g_Blo [128][1024] bf16
// ---------------------------------------------------------------------------
__global__ void convertB_kernel(const float* __restrict__ proj)
{
    __shared__ float tile[32][33];
    const int tx = threadIdx.x, ty = threadIdx.y;      // (32,8)
    const int k0 = blockIdx.x * 32, n0 = blockIdx.y * 32;
    #pragma unroll
    for (int i = 0; i < 4; i++)
        tile[ty + 8 * i][tx] = proj[(size_t)(k0 + ty + 8 * i) * RANK + n0 + tx];
    __syncthreads();
    #pragma unroll
    for (int i = 0; i < 4; i++) {
        int n = n0 + ty + 8 * i, k = k0 + tx;
        float v = tile[tx][ty + 8 * i];
        __nv_bfloat16 h = __float2bfloat16(v);
        __nv_bfloat16 l = __float2bfloat16(v - __bfloat162float(h));
        g_Bhi[(size_t)n * MDIM + k] = h;
        g_Blo[(size_t)n * MDIM + k] = l;
    }
}

// ---------------------------------------------------------------------------
// Kernel 1: mma.sync bf16-split GEMM. grid (KSPLIT, 64), 256 thr.
// CTA: M=64 rows, N=128, K=KS(256) in 4 chunks of 64.
// 8 warps = 4(m)x2(n); warp tile 16x64. acc(f32) += Ahi*Bhi + Ahi*Blo + Alo*Bhi.
// smem rows padded to 144B.
// ---------------------------------------------------------------------------
#define AHI_OFF 0
#define ALO_OFF 9216
#define BHI_OFF 18432
#define BLO_OFF 36864
#define SMEM_BYTES 55296

__global__ void __launch_bounds__(256) mma_gemm_kernel(const float* __restrict__ A)
{
    extern __shared__ char dsm[];
    const int tid  = threadIdx.x;
    const int wid  = tid >> 5, lane = tid & 31;
    const int split = blockIdx.x;
    const int mb    = blockIdx.y * 64;
    const int kbase = split * KS;

    const int warp_m = (wid & 3) * 16;
    const int warp_n = (wid >> 2) * 64;

    const uint32_t smem = sm2u32(dsm);
    const uint32_t a_off = (uint32_t)(warp_m + (lane & 15)) * 144 + (lane >> 4) * 16;
    const uint32_t aaddr_hi = smem + AHI_OFF + a_off;
    const uint32_t aaddr_lo = smem + ALO_OFF + a_off;
    const uint32_t b_noff = ((lane >> 3) & 1) * 8 + (lane & 7);
    const uint32_t b_off  = (uint32_t)(warp_n + b_noff) * 144 + (lane >> 4) * 16;
    const uint32_t baddr_hi = smem + BHI_OFF + b_off;
    const uint32_t baddr_lo = smem + BLO_OFF + b_off;

    float acc[8][4];
    #pragma unroll
    for (int i = 0; i < 8; i++)
        #pragma unroll
        for (int j = 0; j < 4; j++) acc[i][j] = 0.0f;

    for (int c = 0; c < CHUNKS; c++) {
        if (c) __syncthreads();

        #pragma unroll
        for (int t = 0; t < 4; t++) {
            int idx = tid + t * 256;
            int r = idx >> 4, k4 = idx & 15;
            float4 v = *(const float4*)&A[(size_t)(mb + r) * MDIM + kbase + c * KC + k4 * 4];
            __nv_bfloat16 h0 = __float2bfloat16(v.x);
            __nv_bfloat16 h1 = __float2bfloat16(v.y);
            __nv_bfloat16 h2 = __float2bfloat16(v.z);
            __nv_bfloat16 h3 = __float2bfloat16(v.w);
            union { __nv_bfloat162 b2[2]; unsigned long long u; } ph, pl;
            ph.b2[0] = __nv_bfloat162(h0, h1);
            ph.b2[1] = __nv_bfloat162(h2, h3);
            pl.b2[0] = __nv_bfloat162(__float2bfloat16(v.x - __bfloat162float(h0)),
                                      __float2bfloat16(v.y - __bfloat162float(h1)));
            pl.b2[1] = __nv_bfloat162(__float2bfloat16(v.z - __bfloat162float(h2)),
                                      __float2bfloat16(v.w - __bfloat162float(h3)));
            *(unsigned long long*)(dsm + AHI_OFF + r * 144 + k4 * 8) = ph.u;
            *(unsigned long long*)(dsm + ALO_OFF + r * 144 + k4 * 8) = pl.u;
        }
        #pragma unroll
        for (int t = 0; t < 4; t++) {
            int idx = tid + t * 256;
            int n = idx >> 3, g = idx & 7;
            size_t src = (size_t)n * MDIM + kbase + c * KC + g * 8;
            *(uint4*)(dsm + BHI_OFF + n * 144 + g * 16) = *(const uint4*)&g_Bhi[src];
            *(uint4*)(dsm + BLO_OFF + n * 144 + g * 16) = *(const uint4*)&g_Blo[src];
        }
        __syncthreads();

        #pragma unroll
        for (int kk = 0; kk < 4; kk++) {
            uint32_t ah[4], al[4];
            LDMX4(ah, aaddr_hi + kk * 32);
            LDMX4(al, aaddr_lo + kk * 32);
            #pragma unroll
            for (int nn = 0; nn < 4; nn++) {
                uint32_t bh[4], bl[4];
                LDMX4(bh, baddr_hi + nn * 16 * 144 + kk * 32);
                LDMX4(bl, baddr_lo + nn * 16 * 144 + kk * 32);
                float* c0 = acc[nn * 2];
                float* c1 = acc[nn * 2 + 1];
                mma_bf16(c0, ah, bh[0], bh[2]);
                mma_bf16(c0, ah, bl[0], bl[2]);
                mma_bf16(c0, al, bh[0], bh[2]);
                mma_bf16(c1, ah, bh[1], bh[3]);
                mma_bf16(c1, ah, bl[1], bl[3]);
                mma_bf16(c1, al, bh[1], bh[3]);
            }
        }
    }

    float* __restrict__ P = g_Tp[split];
    const int m0 = mb + warp_m + (lane >> 2);
    #pragma unroll
    for (int ch = 0; ch < 8; ch++) {
        int n = warp_n + ch * 8 + (lane & 3) * 2;
        *(float2*)&P[(size_t)m0 * RANK + n] = make_float2(acc[ch][0], acc[ch][1]);
        *(float2*)&P[(size_t)(m0 + 8) * RANK + n] = make_float2(acc[ch][2], acc[ch][3]);
    }
}

// ---------------------------------------------------------------------------
// Kernel 2: combine K-split partials -> bf16 hi/lo T + per-row squared norms.
// ---------------------------------------------------------------------------
__global__ void __launch_bounds__(256) combine_kernel()
{
    int idx = blockIdx.x * 256 + threadIdx.x;      // float4 index
    const float4* p0 = (const float4*)g_Tp[0];
    const float4* p1 = (const float4*)g_Tp[1];
    const float4* p2 = (const float4*)g_Tp[2];
    const float4* p3 = (const float4*)g_Tp[3];
    float4 a = p0[idx], b = p1[idx], c = p2[idx], d = p3[idx];
    float4 v;
    v.x = a.x + b.x + c.x + d.x;
    v.y = a.y + b.y + c.y + d.y;
    v.z = a.z + b.z + c.z + d.z;
    v.w = a.w + b.w + c.w + d.w;

    __nv_bfloat16 h0 = __float2bfloat16(v.x);
    __nv_bfloat16 h1 = __float2bfloat16(v.y);
    __nv_bfloat16 h2 = __float2bfloat16(v.z);
    __nv_bfloat16 h3 = __float2bfloat16(v.w);
    union { __nv_bfloat162 b2[2]; uint2 u; } ph, pl;
    ph.b2[0] = __nv_bfloat162(h0, h1);
    ph.b2[1] = __nv_bfloat162(h2, h3);
    pl.b2[0] = __nv_bfloat162(__float2bfloat16(v.x - __bfloat162float(h0)),
                              __float2bfloat16(v.y - __bfloat162float(h1)));
    pl.b2[1] = __nv_bfloat162(__float2bfloat16(v.z - __bfloat162float(h2)),
                              __float2bfloat16(v.w - __bfloat162float(h3)));
    *(uint2*)&g_Thi[(size_t)idx * 4] = ph.u;
    *(uint2*)&g_Tlo[(size_t)idx * 4] = pl.u;

    float sq = v.x * v.x + v.y * v.y + v.z * v.z + v.w * v.w;
    #pragma unroll
    for (int off = 16; off > 0; off >>= 1)
        sq += __shfl_down_sync(0xffffffffu, sq, off);
    if ((threadIdx.x & 31) == 0)
        g_norm[idx >> 5] = sq;                     // 32 float4 per row
}

// ---------------------------------------------------------------------------
// Kernel 3: pdist via mma.sync bf16 hi/lo Gram.
// CTA: 128(i) x 128(j) tile, full K=128 in smem. grid (4,4,8), 256 thr.
// 8 warps = 4(m)x2(n); warp tile 32x64.
// d(i,j) = n_i + n_j - 2*(Ihi·Jhi + Ihi·Jlo + Ilo·Jhi); diag forced to 0.
// smem rows 272B (128 k * 2B + 16 pad); 272 % 128 = 16 -> ldmatrix conflict-free.
// ---------------------------------------------------------------------------
#define PD_IH 0
#define PD_IL 34816
#define PD_JH 69632
#define PD_JL 104448
#define PD_SMEM 139264
#define PD_STR 272

__global__ void __launch_bounds__(256) pdist_mma_kernel(float* __restrict__ out)
{
    extern __shared__ char dsm[];
    const int tid  = threadIdx.x;
    const int wid  = tid >> 5, lane = tid & 31;
    const int bj = blockIdx.x, bi = blockIdx.y, b = blockIdx.z;
    const int i0 = bi * 128, j0 = bj * 128;
    const bool diag = (bi == bj);

    const __nv_bfloat16* __restrict__ TH = g_Thi + (size_t)b * SEQ * RANK;
    const __nv_bfloat16* __restrict__ TL = g_Tlo + (size_t)b * SEQ * RANK;

    // Stage I (and J if off-diagonal): 128 rows x 128 k bf16, hi+lo.
    #pragma unroll
    for (int t = 0; t < 8; t++) {
        int idx = tid + t * 256;          // 0..2047
        int r = idx >> 4, g = idx & 15;
        size_t si = (size_t)(i0 + r) * RANK + g * 8;
        *(uint4*)(dsm + PD_IH + r * PD_STR + g * 16) = *(const uint4*)&TH[si];
        *(uint4*)(dsm + PD_IL + r * PD_STR + g * 16) = *(const uint4*)&TL[si];
        if (!diag) {
            size_t sj = (size_t)(j0 + r) * RANK + g * 8;
            *(uint4*)(dsm + PD_JH + r * PD_STR + g * 16) = *(const uint4*)&TH[sj];
            *(uint4*)(dsm + PD_JL + r * PD_STR + g * 16) = *(const uint4*)&TL[sj];
        }
    }
    __syncthreads();

    const int warp_m = (wid & 3) * 32;
    const int warp_n = (wid >> 2) * 64;
    const uint32_t smem = sm2u32(dsm);

    const uint32_t ia_off = (uint32_t)(warp_m + (lane & 15)) * PD_STR + (lane >> 4) * 16;
    const uint32_t iaddr_h = smem + PD_IH + ia_off;
    const uint32_t iaddr_l = smem + PD_IL + ia_off;
    const uint32_t j_noff = ((lane >> 3) & 1) * 8 + (lane & 7);
    const uint32_t ja_off = (uint32_t)(warp_n + j_noff) * PD_STR + (lane >> 4) * 16;
    const uint32_t jaddr_h = smem + (diag ? PD_IH : PD_JH) + ja_off;
    const uint32_t jaddr_l = smem + (diag ? PD_IL : PD_JL) + ja_off;

    float acc[2][8][4];
    #pragma unroll
    for (int mf = 0; mf < 2; mf++)
        #pragma unroll
        for (int i = 0; i < 8; i++)
            #pragma unroll
            for (int j = 0; j < 4; j++) acc[mf][i][j] = 0.0f;

    #pragma unroll
    for (int kk = 0; kk < 8; kk++) {
        uint32_t ih[2][4], il[2][4];
        LDMX4(ih[0], iaddr_h + kk * 32);
        LDMX4(ih[1], iaddr_h + 16 * PD_STR + kk * 32);
        LDMX4(il[0], iaddr_l + kk * 32);
        LDMX4(il[1], iaddr_l + 16 * PD_STR + kk * 32);
        #pragma unroll
        for (int nn = 0; nn < 4; nn++) {
            uint32_t jh[4], jl[4];
            LDMX4(jh, jaddr_h + nn * 16 * PD_STR + kk * 32);
            LDMX4(jl, jaddr_l + nn * 16 * PD_STR + kk * 32);
            #pragma unroll
            for (int mf = 0; mf < 2; mf++) {
                float* c0 = acc[mf][nn * 2];
                float* c1 = acc[mf][nn * 2 + 1];
                mma_bf16(c0, ih[mf], jh[0], jh[2]);
                mma_bf16(c0, ih[mf], jl[0], jl[2]);
                mma_bf16(c0, il[mf], jh[0], jh[2]);
                mma_bf16(c1, ih[mf], jh[1], jh[3]);
                mma_bf16(c1, ih[mf], jl[1], jl[3]);
                mma_bf16(c1, il[mf], jh[1], jh[3]);
            }
        }
    }

    // Epilogue: d = n_i + n_j - 2*dot; exact 0 on diagonal.
    const float* __restrict__ nb = g_norm + (size_t)b * SEQ;
    float* __restrict__ ob = out + (size_t)b * SEQ * SEQ;
    #pragma unroll
    for (int mf = 0; mf < 2; mf++) {
        int gi = i0 + warp_m + mf * 16 + (lane >> 2);
        float ni0 = nb[gi], ni1 = nb[gi + 8];
        #pragma unroll
        for (int ch = 0; ch < 8; ch++) {
            int gj = j0 + warp_n + ch * 8 + (lane & 3) * 2;
            float nj0 = nb[gj], nj1 = nb[gj + 1];
            float* a = acc[mf][ch];
            float v00 = ni0 + nj0 - 2.0f * a[0];
            float v01 = ni0 + nj1 - 2.0f * a[1];
            float v10 = ni1 + nj0 - 2.0f * a[2];
            float v11 = ni1 + nj1 - 2.0f * a[3];
            if (diag) {
                if (gi == gj) v00 = 0.0f;
                if (gi == gj + 1) v01 = 0.0f;
                if (gi + 8 == gj) v10 = 0.0f;
                if (gi + 8 == gj + 1) v11 = 0.0f;
            }
            *(float2*)&ob[(size_t)gi * SEQ + gj] = make_float2(v00, v01);
            *(float2*)&ob[(size_t)(gi + 8) * SEQ + gj] = make_float2(v10, v11);
        }
    }
}

extern "C" void kernel_launch(void* const* d_in, const int* in_sizes, int n_in,
                              void* d_out, int out_size)
{
    const float* batch = (const float*)d_in[0];   // [8,512,1024]
    const float* proj  = (const float*)d_in[1];   // [1024,128]
    float* out = (float*)d_out;                   // [8,512,512]

    // Idempotent; first call happens on the correctness run (outside capture).
    cudaFuncSetAttribute(mma_gemm_kernel,
                         cudaFuncAttributeMaxDynamicSharedMemorySize, SMEM_BYTES);
    cudaFuncSetAttribute(pdist_mma_kernel,
                         cudaFuncAttributeMaxDynamicSharedMemorySize, PD_SMEM);

    convertB_kernel<<<dim3(MDIM / 32, RANK / 32), dim3(32, 8)>>>(proj);
    mma_gemm_kernel<<<dim3(KSPLIT, NROWS / 64), 256, SMEM_BYTES>>>(batch);
    combine_kernel<<<NROWS * RANK / 4 / 256, 256>>>();
    pdist_mma_kernel<<<dim3(4, 4, 8), 256, PD_SMEM>>>(out);
}

// round 8
// speedup vs baseline: 2.7281x; 1.0563x over previous
#include <cuda_runtime.h>
#include <cuda_bf16.h>
#include <cstdint>

#define MDIM 1024
#define RANK 128
#define NBATCH 8
#define SEQ 512
#define NROWS (NBATCH * SEQ)          // 4096
#define KSPLIT 4
#define KS (MDIM / KSPLIT)            // 256
#define KC 64                         // k per smem chunk (gemm)
#define CHUNKS (KS / KC)              // 4

// Scratch (static __device__ globals; no allocations allowed).
__device__ float g_Tp[KSPLIT][NROWS * RANK];        // K-split partials, 8 MB
__device__ float g_norm[NROWS];                     // row squared norms
__device__ __nv_bfloat16 g_Bhi[RANK * MDIM];        // B^T hi: [n][k]
__device__ __nv_bfloat16 g_Blo[RANK * MDIM];        // B^T lo: [n][k]
__device__ __nv_bfloat16 g_Thi[NROWS * RANK];       // T hi: [row][k]
__device__ __nv_bfloat16 g_Tlo[NROWS * RANK];       // T lo: [row][k]

// ---------------- helpers ----------------
__device__ __forceinline__ uint32_t sm2u32(const void* p) {
    uint32_t a;
    asm("{ .reg .u64 t; cvta.to.shared.u64 t, %1; cvt.u32.u64 %0, t; }"
        : "=r"(a) : "l"(p));
    return a;
}
#define LDMX4(r, addr) \
    asm volatile("ldmatrix.sync.aligned.m8n8.x4.shared.b16 {%0,%1,%2,%3}, [%4];" \
        : "=r"((r)[0]), "=r"((r)[1]), "=r"((r)[2]), "=r"((r)[3]) : "r"(addr))

__device__ __forceinline__ void mma_bf16(float* c, const uint32_t* a,
                                         uint32_t b0, uint32_t b1) {
    asm volatile(
        "mma.sync.aligned.m16n8k16.row.col.f32.bf16.bf16.f32 "
        "{%0,%1,%2,%3}, {%4,%5,%6,%7}, {%8,%9}, {%0,%1,%2,%3};"
        : "+f"(c[0]), "+f"(c[1]), "+f"(c[2]), "+f"(c[3])
        : "r"(a[0]), "r"(a[1]), "r"(a[2]), "r"(a[3]), "r"(b0), "r"(b1));
}

// ---------------------------------------------------------------------------
// Kernel 0: transpose+split proj [1024,128] fp32 -> g_Bhi/g_Blo [128][1024] bf16
// ---------------------------------------------------------------------------
__global__ void convertB_kernel(const float* __restrict__ proj)
{
    __shared__ float tile[32][33];
    const int tx = threadIdx.x, ty = threadIdx.y;      // (32,8)
    const int k0 = blockIdx.x * 32, n0 = blockIdx.y * 32;
    #pragma unroll
    for (int i = 0; i < 4; i++)
        tile[ty + 8 * i][tx] = proj[(size_t)(k0 + ty + 8 * i) * RANK + n0 + tx];
    __syncthreads();
    #pragma unroll
    for (int i = 0; i < 4; i++) {
        int n = n0 + ty + 8 * i, k = k0 + tx;
        float v = tile[tx][ty + 8 * i];
        __nv_bfloat16 h = __float2bfloat16(v);
        __nv_bfloat16 l = __float2bfloat16(v - __bfloat162float(h));
        g_Bhi[(size_t)n * MDIM + k] = h;
        g_Blo[(size_t)n * MDIM + k] = l;
    }
}

// ---------------------------------------------------------------------------
// Kernel 1: mma.sync bf16-split GEMM. grid (KSPLIT, 64), 512 thr (16 warps).
// CTA: M=64 rows, N=128, K=KS(256) in 4 chunks of 64.
// Warp grid 4(m)x4(n); warp tile 16x32. acc(f32) += Ahi*Bhi + Ahi*Blo + Alo*Bhi.
// smem rows padded to 144B.
// ---------------------------------------------------------------------------
#define AHI_OFF 0
#define ALO_OFF 9216
#define BHI_OFF 18432
#define BLO_OFF 36864
#define SMEM_BYTES 55296

__global__ void __launch_bounds__(512) mma_gemm_kernel(const float* __restrict__ A)
{
    extern __shared__ char dsm[];
    const int tid  = threadIdx.x;
    const int wid  = tid >> 5, lane = tid & 31;
    const int split = blockIdx.x;
    const int mb    = blockIdx.y * 64;
    const int kbase = split * KS;

    const int warp_m = (wid & 3) * 16;
    const int warp_n = (wid >> 2) * 32;

    const uint32_t smem = sm2u32(dsm);
    const uint32_t a_off = (uint32_t)(warp_m + (lane & 15)) * 144 + (lane >> 4) * 16;
    const uint32_t aaddr_hi = smem + AHI_OFF + a_off;
    const uint32_t aaddr_lo = smem + ALO_OFF + a_off;
    const uint32_t b_noff = ((lane >> 3) & 1) * 8 + (lane & 7);
    const uint32_t b_off  = (uint32_t)(warp_n + b_noff) * 144 + (lane >> 4) * 16;
    const uint32_t baddr_hi = smem + BHI_OFF + b_off;
    const uint32_t baddr_lo = smem + BLO_OFF + b_off;

    float acc[4][4];
    #pragma unroll
    for (int i = 0; i < 4; i++)
        #pragma unroll
        for (int j = 0; j < 4; j++) acc[i][j] = 0.0f;

    for (int c = 0; c < CHUNKS; c++) {
        if (c) __syncthreads();

        // A chunk [64][64] fp32 -> bf16 hi/lo into smem (1024 float4, 2/thread)
        #pragma unroll
        for (int t = 0; t < 2; t++) {
            int idx = tid + t * 512;
            int r = idx >> 4, k4 = idx & 15;
            float4 v = *(const float4*)&A[(size_t)(mb + r) * MDIM + kbase + c * KC + k4 * 4];
            __nv_bfloat16 h0 = __float2bfloat16(v.x);
            __nv_bfloat16 h1 = __float2bfloat16(v.y);
            __nv_bfloat16 h2 = __float2bfloat16(v.z);
            __nv_bfloat16 h3 = __float2bfloat16(v.w);
            union { __nv_bfloat162 b2[2]; unsigned long long u; } ph, pl;
            ph.b2[0] = __nv_bfloat162(h0, h1);
            ph.b2[1] = __nv_bfloat162(h2, h3);
            pl.b2[0] = __nv_bfloat162(__float2bfloat16(v.x - __bfloat162float(h0)),
                                      __float2bfloat16(v.y - __bfloat162float(h1)));
            pl.b2[1] = __nv_bfloat162(__float2bfloat16(v.z - __bfloat162float(h2)),
                                      __float2bfloat16(v.w - __bfloat162float(h3)));
            *(unsigned long long*)(dsm + AHI_OFF + r * 144 + k4 * 8) = ph.u;
            *(unsigned long long*)(dsm + ALO_OFF + r * 144 + k4 * 8) = pl.u;
        }
        // B chunk [128][64] bf16 hi/lo (1024 uint4, 2/thread)
        #pragma unroll
        for (int t = 0; t < 2; t++) {
            int idx = tid + t * 512;
            int n = idx >> 3, g = idx & 7;
            size_t src = (size_t)n * MDIM + kbase + c * KC + g * 8;
            *(uint4*)(dsm + BHI_OFF + n * 144 + g * 16) = *(const uint4*)&g_Bhi[src];
            *(uint4*)(dsm + BLO_OFF + n * 144 + g * 16) = *(const uint4*)&g_Blo[src];
        }
        __syncthreads();

        #pragma unroll
        for (int kk = 0; kk < 4; kk++) {
            uint32_t ah[4], al[4];
            LDMX4(ah, aaddr_hi + kk * 32);
            LDMX4(al, aaddr_lo + kk * 32);
            #pragma unroll
            for (int nn = 0; nn < 2; nn++) {
                uint32_t bh[4], bl[4];
                LDMX4(bh, baddr_hi + nn * 16 * 144 + kk * 32);
                LDMX4(bl, baddr_lo + nn * 16 * 144 + kk * 32);
                float* c0 = acc[nn * 2];
                float* c1 = acc[nn * 2 + 1];
                mma_bf16(c0, ah, bh[0], bh[2]);
                mma_bf16(c0, ah, bl[0], bl[2]);
                mma_bf16(c0, al, bh[0], bh[2]);
                mma_bf16(c1, ah, bh[1], bh[3]);
                mma_bf16(c1, ah, bl[1], bl[3]);
                mma_bf16(c1, al, bh[1], bh[3]);
            }
        }
    }

    float* __restrict__ P = g_Tp[split];
    const int m0 = mb + warp_m + (lane >> 2);
    #pragma unroll
    for (int ch = 0; ch < 4; ch++) {
        int n = warp_n + ch * 8 + (lane & 3) * 2;
        *(float2*)&P[(size_t)m0 * RANK + n] = make_float2(acc[ch][0], acc[ch][1]);
        *(float2*)&P[(size_t)(m0 + 8) * RANK + n] = make_float2(acc[ch][2], acc[ch][3]);
    }
}

// ---------------------------------------------------------------------------
// Kernel 2: combine K-split partials -> bf16 hi/lo T + per-row squared norms.
// ---------------------------------------------------------------------------
__global__ void __launch_bounds__(256) combine_kernel()
{
    int idx = blockIdx.x * 256 + threadIdx.x;      // float4 index
    const float4* p0 = (const float4*)g_Tp[0];
    const float4* p1 = (const float4*)g_Tp[1];
    const float4* p2 = (const float4*)g_Tp[2];
    const float4* p3 = (const float4*)g_Tp[3];
    float4 a = p0[idx], b = p1[idx], c = p2[idx], d = p3[idx];
    float4 v;
    v.x = a.x + b.x + c.x + d.x;
    v.y = a.y + b.y + c.y + d.y;
    v.z = a.z + b.z + c.z + d.z;
    v.w = a.w + b.w + c.w + d.w;

    __nv_bfloat16 h0 = __float2bfloat16(v.x);
    __nv_bfloat16 h1 = __float2bfloat16(v.y);
    __nv_bfloat16 h2 = __float2bfloat16(v.z);
    __nv_bfloat16 h3 = __float2bfloat16(v.w);
    union { __nv_bfloat162 b2[2]; uint2 u; } ph, pl;
    ph.b2[0] = __nv_bfloat162(h0, h1);
    ph.b2[1] = __nv_bfloat162(h2, h3);
    pl.b2[0] = __nv_bfloat162(__float2bfloat16(v.x - __bfloat162float(h0)),
                              __float2bfloat16(v.y - __bfloat162float(h1)));
    pl.b2[1] = __nv_bfloat162(__float2bfloat16(v.z - __bfloat162float(h2)),
                              __float2bfloat16(v.w - __bfloat162float(h3)));
    *(uint2*)&g_Thi[(size_t)idx * 4] = ph.u;
    *(uint2*)&g_Tlo[(size_t)idx * 4] = pl.u;

    float sq = v.x * v.x + v.y * v.y + v.z * v.z + v.w * v.w;
    #pragma unroll
    for (int off = 16; off > 0; off >>= 1)
        sq += __shfl_down_sync(0xffffffffu, sq, off);
    if ((threadIdx.x & 31) == 0)
        g_norm[idx >> 5] = sq;                     // 32 float4 per row
}

// ---------------------------------------------------------------------------
// Kernel 3: pdist via mma.sync bf16 hi/lo Gram.
// CTA: 128(i) x 128(j) tile, full K=128 in smem. grid (4,4,8), 512 thr.
// Warp grid 4(m)x4(n); warp tile 32x32.
// d(i,j) = n_i + n_j - 2*(Ihi·Jhi + Ihi·Jlo + Ilo·Jhi); diag forced to 0.
// smem rows 272B; 272 % 128 = 16 -> ldmatrix conflict-free.
// ---------------------------------------------------------------------------
#define PD_IH 0
#define PD_IL 34816
#define PD_JH 69632
#define PD_JL 104448
#define PD_SMEM 139264
#define PD_STR 272

__global__ void __launch_bounds__(512) pdist_mma_kernel(float* __restrict__ out)
{
    extern __shared__ char dsm[];
    const int tid  = threadIdx.x;
    const int wid  = tid >> 5, lane = tid & 31;
    const int bj = blockIdx.x, bi = blockIdx.y, b = blockIdx.z;
    const int i0 = bi * 128, j0 = bj * 128;
    const bool diag = (bi == bj);

    const __nv_bfloat16* __restrict__ TH = g_Thi + (size_t)b * SEQ * RANK;
    const __nv_bfloat16* __restrict__ TL = g_Tlo + (size_t)b * SEQ * RANK;

    // Stage I (and J if off-diagonal): 128 rows x 128 k bf16, hi+lo.
    #pragma unroll
    for (int t = 0; t < 4; t++) {
        int idx = tid + t * 512;          // 0..2047
        int r = idx >> 4, g = idx & 15;
        size_t si = (size_t)(i0 + r) * RANK + g * 8;
        *(uint4*)(dsm + PD_IH + r * PD_STR + g * 16) = *(const uint4*)&TH[si];
        *(uint4*)(dsm + PD_IL + r * PD_STR + g * 16) = *(const uint4*)&TL[si];
        if (!diag) {
            size_t sj = (size_t)(j0 + r) * RANK + g * 8;
            *(uint4*)(dsm + PD_JH + r * PD_STR + g * 16) = *(const uint4*)&TH[sj];
            *(uint4*)(dsm + PD_JL + r * PD_STR + g * 16) = *(const uint4*)&TL[sj];
        }
    }
    __syncthreads();

    const int warp_m = (wid & 3) * 32;
    const int warp_n = (wid >> 2) * 32;
    const uint32_t smem = sm2u32(dsm);

    const uint32_t ia_off = (uint32_t)(warp_m + (lane & 15)) * PD_STR + (lane >> 4) * 16;
    const uint32_t iaddr_h = smem + PD_IH + ia_off;
    const uint32_t iaddr_l = smem + PD_IL + ia_off;
    const uint32_t j_noff = ((lane >> 3) & 1) * 8 + (lane & 7);
    const uint32_t ja_off = (uint32_t)(warp_n + j_noff) * PD_STR + (lane >> 4) * 16;
    const uint32_t jaddr_h = smem + (diag ? PD_IH : PD_JH) + ja_off;
    const uint32_t jaddr_l = smem + (diag ? PD_IL : PD_JL) + ja_off;

    float acc[2][4][4];
    #pragma unroll
    for (int mf = 0; mf < 2; mf++)
        #pragma unroll
        for (int i = 0; i < 4; i++)
            #pragma unroll
            for (int j = 0; j < 4; j++) acc[mf][i][j] = 0.0f;

    #pragma unroll
    for (int kk = 0; kk < 8; kk++) {
        uint32_t ih[2][4], il[2][4];
        LDMX4(ih[0], iaddr_h + kk * 32);
        LDMX4(ih[1], iaddr_h + 16 * PD_STR + kk * 32);
        LDMX4(il[0], iaddr_l + kk * 32);
        LDMX4(il[1], iaddr_l + 16 * PD_STR + kk * 32);
        #pragma unroll
        for (int nn = 0; nn < 2; nn++) {
            uint32_t jh[4], jl[4];
            LDMX4(jh, jaddr_h + nn * 16 * PD_STR + kk * 32);
            LDMX4(jl, jaddr_l + nn * 16 * PD_STR + kk * 32);
            #pragma unroll
            for (int mf = 0; mf < 2; mf++) {
                float* c0 = acc[mf][nn * 2];
                float* c1 = acc[mf][nn * 2 + 1];
                mma_bf16(c0, ih[mf], jh[0], jh[2]);
                mma_bf16(c0, ih[mf], jl[0], jl[2]);
                mma_bf16(c0, il[mf], jh[0], jh[2]);
                mma_bf16(c1, ih[mf], jh[1], jh[3]);
                mma_bf16(c1, ih[mf], jl[1], jl[3]);
                mma_bf16(c1, il[mf], jh[1], jh[3]);
            }
        }
    }

    // Epilogue: d = n_i + n_j - 2*dot; exact 0 on diagonal.
    const float* __restrict__ nb = g_norm + (size_t)b * SEQ;
    float* __restrict__ ob = out + (size_t)b * SEQ * SEQ;
    #pragma unroll
    for (int mf = 0; mf < 2; mf++) {
        int gi = i0 + warp_m + mf * 16 + (lane >> 2);
        float ni0 = nb[gi], ni1 = nb[gi + 8];
        #pragma unroll
        for (int ch = 0; ch < 4; ch++) {
            int gj = j0 + warp_n + ch * 8 + (lane & 3) * 2;
            float nj0 = nb[gj], nj1 = nb[gj + 1];
            float* a = acc[mf][ch];
            float v00 = ni0 + nj0 - 2.0f * a[0];
            float v01 = ni0 + nj1 - 2.0f * a[1];
            float v10 = ni1 + nj0 - 2.0f * a[2];
            float v11 = ni1 + nj1 - 2.0f * a[3];
            if (diag) {
                if (gi == gj) v00 = 0.0f;
                if (gi == gj + 1) v01 = 0.0f;
                if (gi + 8 == gj) v10 = 0.0f;
                if (gi + 8 == gj + 1) v11 = 0.0f;
            }
            *(float2*)&ob[(size_t)gi * SEQ + gj] = make_float2(v00, v01);
            *(float2*)&ob[(size_t)(gi + 8) * SEQ + gj] = make_float2(v10, v11);
        }
    }
}

extern "C" void kernel_launch(void* const* d_in, const int* in_sizes, int n_in,
                              void* d_out, int out_size)
{
    const float* batch = (const float*)d_in[0];   // [8,512,1024]
    const float* proj  = (const float*)d_in[1];   // [1024,128]
    float* out = (float*)d_out;                   // [8,512,512]

    // Idempotent; first call happens on the correctness run (outside capture).
    cudaFuncSetAttribute(mma_gemm_kernel,
                         cudaFuncAttributeMaxDynamicSharedMemorySize, SMEM_BYTES);
    cudaFuncSetAttribute(pdist_mma_kernel,
                         cudaFuncAttributeMaxDynamicSharedMemorySize, PD_SMEM);

    convertB_kernel<<<dim3(MDIM / 32, RANK / 32), dim3(32, 8)>>>(proj);
    mma_gemm_kernel<<<dim3(KSPLIT, NROWS / 64), 512, SMEM_BYTES>>>(batch);
    combine_kernel<<<NROWS * RANK / 4 / 256, 256>>>();
    pdist_mma_kernel<<<dim3(4, 4, 8), 512, PD_SMEM>>>(out);
}